// round 5
// baseline (speedup 1.0000x reference)
#include <cuda_runtime.h>
#include <math.h>

#define BATCH 2
#define TLEN  2048
#define DIM   256
#define CD    64
#define TC    512
#define SEQ   (TC + TLEN)
#define KTOP  8

static __device__ __forceinline__ float fneginf() { return __int_as_float(0xff800000); }

// ----------------------------- scratch ------------------------------------
__device__ float g_Q  [BATCH * TLEN * DIM];    // roped Q, [b][t][h*64+c]
__device__ float g_K  [BATCH * SEQ * CD];      // roped K over concat axis
__device__ float g_V  [BATCH * SEQ * CD];
__device__ float g_QI [BATCH * TLEN * 128];
__device__ float g_WIw[BATCH * TLEN * 4];
__device__ float g_KI [BATCH * TC * 32];
__device__ float g_cos[SEQ * 32];
__device__ float g_sin[SEQ * 32];

// ----------------------------- K0: rope tables -----------------------------
__global__ void k_tables()
{
    int idx = blockIdx.x * blockDim.x + threadIdx.x;
    if (idx >= SEQ * 32) return;
    int pos = idx >> 5, j = idx & 31;
    float invf = (float)pow(10000.0, -(double)j / 32.0);   // f32-rounded inv_freq
    float ang  = (float)pos * invf;                        // f32 angle (matches ref)
    double a = (double)ang;
    g_cos[idx] = (float)cos(a);
    g_sin[idx] = (float)sin(a);
}

// ------------------ K1: fused token GEMMs + window compression -------------
__global__ __launch_bounds__(384) void k_pre(
    const float* __restrict__ H,
    const float* __restrict__ Wc_comp, const float* __restrict__ Wc_idx,
    const float* __restrict__ W_DQ, const float* __restrict__ W_IUQ,
    const float* __restrict__ W_w,  const float* __restrict__ W_Q,
    const float* __restrict__ W_KV,
    const float* __restrict__ gq, const float* __restrict__ gk,
    const float* __restrict__ gv)
{
    __shared__ float sm[11272];
    const int tid = threadIdx.x;

    if (blockIdx.x < 256) {
        // ======================= token path ================================
        float* h_s   = sm;          // [k][tok]  4096
        float* o_s   = sm + 4096;   // [tok][col] 6144
        float* rq_s  = sm + 10240;  // 64
        float* rkv_s = sm + 10304;  // 16
        const int b  = blockIdx.x >> 7;
        const int t0 = (blockIdx.x & 127) << 4;
        const float* Hb = H + ((size_t)b * TLEN + t0) * DIM;

        for (int i = tid; i < 16 * DIM; i += 384)
            h_s[(i & 255) * 16 + (i >> 8)] = Hb[i];
        __syncthreads();

        float acc[16];
#pragma unroll
        for (int i = 0; i < 16; i++) acc[i] = 0.f;
        const float* Wcol; int ldw;
        if (tid < 256)      { Wcol = W_Q  + tid;         ldw = 256; }
        else if (tid < 320) { Wcol = W_KV + (tid - 256); ldw = 64;  }
        else                { Wcol = W_DQ + (tid - 320); ldw = 64;  }
#pragma unroll 4
        for (int k = 0; k < DIM; k++) {
            float w = Wcol[(size_t)k * ldw];
            const float4* hr = (const float4*)(h_s + k * 16);
#pragma unroll
            for (int q = 0; q < 4; q++) {
                float4 a = hr[q];
                acc[4*q+0] += a.x * w; acc[4*q+1] += a.y * w;
                acc[4*q+2] += a.z * w; acc[4*q+3] += a.w * w;
            }
        }
#pragma unroll
        for (int tok = 0; tok < 16; tok++) o_s[tok * 384 + tid] = acc[tok];
        __syncthreads();

        if (tid < 64) {
            int tok = tid >> 2, h = tid & 3;
            float ss = 0.f;
            for (int c = 0; c < CD; c++) { float v = o_s[tok*384 + h*64 + c]; ss += v*v; }
            rq_s[tid] = rsqrtf(ss * (1.f/64.f) + 1e-6f);
        } else if (tid < 80) {
            int tok = tid - 64;
            float ss = 0.f;
            for (int c = 0; c < CD; c++) { float v = o_s[tok*384 + 256 + c]; ss += v*v; }
            rkv_s[tok] = rsqrtf(ss * (1.f/64.f) + 1e-6f);
        }
        __syncthreads();

        for (int i = tid; i < 16 * 256; i += 384) {
            int tok = i >> 8, cc = i & 255;
            int h = cc >> 6, c = cc & 63, j = c & 31;
            int t = t0 + tok;
            float r = rq_s[tok * 4 + h];
            float x1 = o_s[tok*384 + h*64 + j]      * r * gq[h*64 + j];
            float x2 = o_s[tok*384 + h*64 + j + 32] * r * gq[h*64 + j + 32];
            float cs = g_cos[t*32 + j], sn = g_sin[t*32 + j];
            g_Q[((size_t)b*TLEN + t) * 256 + cc] = (c < 32) ? (x1*cs - x2*sn)
                                                            : (x1*sn + x2*cs);
        }
        for (int i = tid; i < 16 * 64; i += 384) {
            int tok = i >> 6, c = i & 63, j = c & 31;
            int t = t0 + tok, pos = TC + t;
            float r = rkv_s[tok];
            float x1 = o_s[tok*384 + 256 + j]      * r;
            float x2 = o_s[tok*384 + 256 + j + 32] * r;
            float cs = g_cos[pos*32 + j], sn = g_sin[pos*32 + j];
            float k1 = x1*gk[j], k2 = x2*gk[j+32];
            float v1 = x1*gv[j], v2 = x2*gv[j+32];
            size_t o = ((size_t)b*SEQ + pos) * 64 + c;
            g_K[o] = (c < 32) ? (k1*cs - k2*sn) : (k1*sn + k2*cs);
            g_V[o] = (c < 32) ? (v1*cs - v2*sn) : (v1*sn + v2*cs);
        }
        for (int i = tid; i < 16 * 128; i += 384) {
            int tok = i >> 7, c = i & 127;
            const float* hd = &o_s[tok*384 + 320];
            float a = 0.f;
#pragma unroll 4
            for (int k = 0; k < 64; k++) a += hd[k] * W_IUQ[k*128 + c];
            g_QI[((size_t)b*TLEN + t0 + tok) * 128 + c] = a;
        }
        if (tid < 64) {
            int tok = tid >> 2, c = tid & 3;
            const float* hd = &o_s[tok*384 + 320];
            float a = 0.f;
            for (int k = 0; k < 64; k++) a += hd[k] * W_w[k*4 + c];
            g_WIw[((size_t)b*TLEN + t0 + tok) * 4 + c] = a;
        }
    } else {
        // ======================= compress path =============================
        float* win    = sm;          // 9216
        float* comp_s = sm + 9216;   // 512
        float* red_s  = sm + 9728;   // 1536
        float* rms_s  = sm + 11264;  // 8
        const int cb = blockIdx.x - 256;
        const int b  = cb >> 6;
        const int s0 = (cb & 63) << 3;
        const int row0 = s0 << 2;

        for (int i = tid; i < 36 * DIM; i += 384) {
            int r = row0 + (i >> 8);
            win[i] = (r < TLEN) ? H[((size_t)b*TLEN + r) * DIM + (i & 255)] : 0.f;
        }
        __syncthreads();

        const int col = tid % 96;
        const int sub = tid / 96;
        const int grp = sub >> 1;
        const int kh  = sub & 1;
        const int ds0 = grp << 2;
        const float* Wcol; int ldw;
        if (col < 64) { Wcol = Wc_comp + col;       ldw = 64; }
        else          { Wcol = Wc_idx + (col - 64); ldw = 32; }

        float a0 = 0.f, a1 = 0.f, a2 = 0.f, a3 = 0.f;
        const int k4b = kh << 8;
        for (int k4 = k4b; k4 < k4b + 256; k4++) {
            float w0 = Wcol[(size_t)(4*k4+0) * ldw];
            float w1 = Wcol[(size_t)(4*k4+1) * ldw];
            float w2 = Wcol[(size_t)(4*k4+2) * ldw];
            float w3 = Wcol[(size_t)(4*k4+3) * ldw];
            int lrow = k4 >> 6;
            int coff = (k4 & 63) << 2;
#pragma unroll
            for (int d = 0; d < 4; d++) {
                const float4 wv = *(const float4*)&win[(4*(ds0+d) + lrow) * DIM + coff];
                float s = wv.x*w0 + wv.y*w1 + wv.z*w2 + wv.w*w3;
                if (d == 0) a0 += s; else if (d == 1) a1 += s;
                else if (d == 2) a2 += s; else a3 += s;
            }
        }
        *(float4*)&red_s[(sub*96 + col) * 4] = make_float4(a0, a1, a2, a3);
        __syncthreads();
        if (kh == 0) {
            float4 mine = *(const float4*)&red_s[(sub*96 + col) * 4];
            float4 othr = *(const float4*)&red_s[((sub+1)*96 + col) * 4];
            float av[4] = { mine.x + othr.x, mine.y + othr.y,
                            mine.z + othr.z, mine.w + othr.w };
#pragma unroll
            for (int d = 0; d < 4; d++) {
                int ds = ds0 + d;
                if (col < 64) comp_s[ds*64 + col] = av[d];
                else g_KI[((size_t)b*TC + s0 + ds) * 32 + (col - 64)] = av[d];
            }
        }
        __syncthreads();
        if (tid < 8) {
            float ss = 0.f;
            for (int c = 0; c < 64; c++) { float v = comp_s[tid*64 + c]; ss += v*v; }
            rms_s[tid] = rsqrtf(ss * (1.f/64.f) + 1e-6f);
        }
        __syncthreads();
        for (int i = tid; i < 8 * 64; i += 384) {
            int ds = i >> 6, c = i & 63, j = c & 31;
            int pos = s0 + ds;
            float r = rms_s[ds];
            float x1 = comp_s[ds*64 + j] * r, x2 = comp_s[ds*64 + j + 32] * r;
            float cs = g_cos[pos*32 + j], sn = g_sin[pos*32 + j];
            float k1 = x1*gk[j], k2 = x2*gk[j+32];
            float v1 = x1*gv[j], v2 = x2*gv[j+32];
            size_t o = ((size_t)b*SEQ + pos) * 64 + c;
            g_K[o] = (c < 32) ? (k1*cs - k2*sn) : (k1*sn + k2*cs);
            g_V[o] = (c < 32) ? (v1*cs - v2*sn) : (v1*sn + v2*cs);
        }
    }
}

// ------------------ K2: fused scores + topk + attention + projections ------
// 512 threads, 16 tokens/block.
// phase-1 smem (floats): qi[0,2112) ki[2112,6208) i_s[6208,14432)
// phase-2 smem:          qo[0,4096) kK[4096,6204) vV[6208,8316)
//                        g_s[8320,10368) p_s[10368,11904)
// persistent:            top_s (ints) at [14432,14560)
#define ISTRIDE 514
#define KVPAD   68
static __device__ __forceinline__ unsigned long long packkey(float v, int s)
{
    unsigned u = __float_as_uint(v);
    u = (u & 0x80000000u) ? ~u : (u | 0x80000000u);
    return ((unsigned long long)u << 32) | (unsigned)(511 - s);
}

__global__ __launch_bounds__(512) void k_main(
    const float* __restrict__ Wg0, const float* __restrict__ bg0,
    const float* __restrict__ Wg1, const float* __restrict__ bg1,
    const float* __restrict__ Wout, const float* __restrict__ bout,
    float* __restrict__ OUT)
{
    extern __shared__ float dsm[];
    float* qi_s = dsm;
    float* ki_s = dsm + 2112;
    float* i_s  = dsm + 6208;
    float* qo_s = dsm;
    float* kK_s = dsm + 4096;
    float* vV_s = dsm + 6208;
    float* g_s  = dsm + 8320;
    float* p_s  = dsm + 10368;
    int*   top_s = (int*)(dsm + 14432);

    const int tid = threadIdx.x;
    const int b  = blockIdx.x >> 7;
    const int r  = blockIdx.x & 127;
    const int t0 = (127 - r) << 4;                 // heavy blocks first
    const int nchunk = ((((t0 + 15) >> 2) + 1) + 127) >> 7;

    // ---------------- phase 1: index scores ----------------
    for (int i = tid; i < 16 * 128; i += 512)
        qi_s[(i >> 7) * 132 + (i & 127)] =
            g_QI[((size_t)b*TLEN + t0 + (i >> 7)) * 128 + (i & 127)];

    const int tok  = tid & 15;
    const int sgrp = tid >> 4;                     // 0..31, 4 s-values each
    const float4 wIw = *(const float4*)&g_WIw[((size_t)b*TLEN + t0 + tok) * 4];

    for (int c = 0; c < nchunk; c++) {
        const int s0 = c << 7;
        __syncthreads();
        for (int i = tid; i < 128 * 32; i += 512)
            ki_s[i] = g_KI[((size_t)b*TC + s0) * 32 + i];
        __syncthreads();

        float acc[4][4];
#pragma unroll
        for (int h = 0; h < 4; h++)
#pragma unroll
            for (int j = 0; j < 4; j++) acc[h][j] = 0.f;
#pragma unroll
        for (int c4 = 0; c4 < 8; c4++) {
            float4 q4[4];
#pragma unroll
            for (int h = 0; h < 4; h++)
                q4[h] = *(const float4*)&qi_s[tok*132 + h*32 + c4*4];
#pragma unroll
            for (int j = 0; j < 4; j++) {
                const float4 kv = *(const float4*)&ki_s[(sgrp*4 + j)*32 + c4*4];
#pragma unroll
                for (int h = 0; h < 4; h++)
                    acc[h][j] += q4[h].x*kv.x + q4[h].y*kv.y + q4[h].z*kv.z + q4[h].w*kv.w;
            }
        }
#pragma unroll
        for (int j = 0; j < 4; j++) {
            float v = wIw.x*fmaxf(acc[0][j],0.f) + wIw.y*fmaxf(acc[1][j],0.f)
                    + wIw.z*fmaxf(acc[2][j],0.f) + wIw.w*fmaxf(acc[3][j],0.f);
            i_s[tok*ISTRIDE + s0 + sgrp*4 + j] = v;
        }
    }
    __syncthreads();

    // ---------------- phase 2a: stage qo + sliding K, and top-k ----------
    for (int i = tid; i < 16 * 256; i += 512)
        qo_s[i] = g_Q[((size_t)b*TLEN + t0) * 256 + i];
    for (int i = tid; i < 31 * 64; i += 512) {
        int rel = i >> 6, c = i & 63;
        int row = TC + t0 - 15 + rel;
        kK_s[rel*KVPAD + c] = (row >= TC) ? g_K[((size_t)b*SEQ + row)*64 + c] : 0.f;
    }
    {   // top-k: warp w -> token t0+w (exact jax.lax.top_k semantics)
        const int w = tid >> 5, l = tid & 31;
        const int t = t0 + w;
        const float* Irow = &i_s[w * ISTRIDE];
        unsigned long long keys[16];
#pragma unroll
        for (int k = 0; k < 16; k++) {
            int s = l + 32*k;
            float v = (4*s <= t) ? Irow[s] : fneginf();
            keys[k] = packkey(v, s);
        }
#pragma unroll 1
        for (int i = 0; i < KTOP; i++) {
            unsigned long long best = 0ull;
#pragma unroll
            for (int k = 0; k < 16; k++) best = max(best, keys[k]);
#pragma unroll
            for (int off = 16; off; off >>= 1)
                best = max(best, __shfl_xor_sync(0xffffffffu, best, off));
            int s_win = 511 - (int)(best & 0xffffffffull);
            if (l == 0) top_s[w*8 + i] = s_win;
            if ((s_win & 31) == l) keys[s_win >> 5] = 0ull;
        }
    }
    __syncthreads();

    // ---------------- phase 2b: stage sliding V (overwrites i_s) ----------
    for (int i = tid; i < 31 * 64; i += 512) {
        int rel = i >> 6, c = i & 63;
        int row = TC + t0 - 15 + rel;
        vV_s[rel*KVPAD + c] = (row >= TC) ? g_V[((size_t)b*SEQ + row)*64 + c] : 0.f;
    }
    __syncthreads();

    // ---------------- phase 3: attention ----------------
    {
        const int w = tid >> 5, l = tid & 31;
        const int t = t0 + w;
        const int nsl = (t + 1 < 16) ? (t + 1) : 16;
        const int nkey = 8 + nsl;

        float dh[4] = {0.f, 0.f, 0.f, 0.f};
        bool valid = false;
        if (l < 8) {
            valid = true;
            int row = top_s[w*8 + l];
            const float4* kp = (const float4*)(g_K + ((size_t)b*SEQ + row) * 64);
#pragma unroll
            for (int c4 = 0; c4 < 16; c4++) {
                float4 kv = kp[c4];
#pragma unroll
                for (int h = 0; h < 4; h++) {
                    float4 q4 = *(const float4*)&qo_s[w*256 + h*64 + c4*4];
                    dh[h] += q4.x*kv.x + q4.y*kv.y + q4.z*kv.z + q4.w*kv.w;
                }
            }
        } else if (l < 24) {
            valid = (l < nkey);
            const float4* kp = (const float4*)(kK_s + (w + 23 - l) * KVPAD);
#pragma unroll
            for (int c4 = 0; c4 < 16; c4++) {
                float4 kv = kp[c4];
#pragma unroll
                for (int h = 0; h < 4; h++) {
                    float4 q4 = *(const float4*)&qo_s[w*256 + h*64 + c4*4];
                    dh[h] += q4.x*kv.x + q4.y*kv.y + q4.z*kv.z + q4.w*kv.w;
                }
            }
        }
#pragma unroll
        for (int h = 0; h < 4; h++) {
            float s = valid ? dh[h] * 0.125f : fneginf();
            float m = s;
#pragma unroll
            for (int off = 16; off; off >>= 1)
                m = fmaxf(m, __shfl_xor_sync(0xffffffffu, m, off));
            float e = expf(s - m);
            float sum = e;
#pragma unroll
            for (int off = 16; off; off >>= 1)
                sum += __shfl_xor_sync(0xffffffffu, sum, off);
            float p = e / sum;                 // 0 for invalid lanes
            if (l < 24) p_s[w*96 + h*24 + l] = p;
        }
        __syncwarp();

        float o1[4] = {0,0,0,0}, o2[4] = {0,0,0,0};
#pragma unroll
        for (int j = 0; j < 8; j++) {          // top-k keys: gmem gather
            int rj = top_s[w*8 + j];
            const float* vp = g_V + ((size_t)b*SEQ + rj) * 64;
            float v1 = vp[l], v2 = vp[l + 32];
#pragma unroll
            for (int h = 0; h < 4; h++) {
                float p = p_s[w*96 + h*24 + j];
                o1[h] += p * v1;
                o2[h] += p * v2;
            }
        }
#pragma unroll
        for (int j = 8; j < 24; j++) {         // sliding keys: smem
            const float* vp = vV_s + (w + 23 - j) * KVPAD;
            float v1 = vp[l], v2 = vp[l + 32];
#pragma unroll
            for (int h = 0; h < 4; h++) {
                float p = p_s[w*96 + h*24 + j];
                o1[h] += p * v1;
                o2[h] += p * v2;
            }
        }
        float cs = g_cos[t*32 + l], sn = g_sin[t*32 + l];
        __syncwarp();   // all lanes done reading qo_s[w] before overwrite
#pragma unroll
        for (int h = 0; h < 4; h++) {
            qo_s[w*256 + h*64 + l]      =  o1[h]*cs + o2[h]*sn;
            qo_s[w*256 + h*64 + 32 + l] = -o1[h]*sn + o2[h]*cs;
        }
    }
    __syncthreads();

    // ---------------- phase 4: gate projections ----------------
    {
        const int col = tid & 127;
        const int tq  = tid >> 7;               // 4 tokens each
        const int c   = col & 63;
        const float* Wg = (col < 64) ? Wg0 : Wg1;
        const float  bb = (col < 64) ? bg0[c] : bg1[c];
        const int obase = (col < 64) ? 0 : 128;
        float a[4] = {bb, bb, bb, bb};
#pragma unroll 4
        for (int k = 0; k < 128; k++) {
            float wv = Wg[k*64 + c];
#pragma unroll
            for (int u = 0; u < 4; u++)
                a[u] += qo_s[(tq*4 + u)*256 + obase + k] * wv;
        }
#pragma unroll
        for (int u = 0; u < 4; u++) g_s[(tq*4 + u)*128 + col] = a[u];
    }
    __syncthreads();

    // ---------------- phase 5: final projection ----------------
    {
        const int col = tid & 255;
        const int tq  = tid >> 8;               // 8 tokens each
        float bb = bout[col];
        float a[8] = {bb, bb, bb, bb, bb, bb, bb, bb};
#pragma unroll 4
        for (int k = 0; k < 128; k++) {
            float wv = Wout[k*256 + col];
#pragma unroll
            for (int u = 0; u < 8; u++)
                a[u] += g_s[(tq*8 + u)*128 + k] * wv;
        }
#pragma unroll
        for (int u = 0; u < 8; u++)
            OUT[((size_t)b*TLEN + t0 + tq*8 + u) * DIM + col] = a[u];
    }
}

// ----------------------------- launcher ------------------------------------
extern "C" void kernel_launch(void* const* d_in, const int* in_sizes, int n_in,
                              void* d_out, int out_size)
{
    const float* H       = (const float*)d_in[0];
    const float* Wc_comp = (const float*)d_in[1];
    const float* Wc_idx  = (const float*)d_in[2];
    const float* W_DQ    = (const float*)d_in[3];
    const float* W_IUQ   = (const float*)d_in[4];
    const float* W_w     = (const float*)d_in[5];
    const float* W_Q     = (const float*)d_in[6];
    const float* W_KV    = (const float*)d_in[7];
    const float* gq      = (const float*)d_in[8];
    const float* gk      = (const float*)d_in[9];
    const float* gv      = (const float*)d_in[10];
    const float* Wg0     = (const float*)d_in[11];
    const float* bg0     = (const float*)d_in[12];
    const float* Wg1     = (const float*)d_in[13];
    const float* bg1     = (const float*)d_in[14];
    const float* Wout    = (const float*)d_in[15];
    const float* bout    = (const float*)d_in[16];
    float* OUT = (float*)d_out;

    static int smem_set = 0;
    if (!smem_set) {
        cudaFuncSetAttribute(k_main,
                             cudaFuncAttributeMaxDynamicSharedMemorySize, 58240);
        smem_set = 1;
    }

    k_tables<<<(SEQ * 32 + 255) / 256, 256>>>();
    k_pre<<<256 + 128, 384>>>(H, Wc_comp, Wc_idx, W_DQ, W_IUQ, W_w, W_Q, W_KV,
                              gq, gk, gv);
    k_main<<<BATCH * 128, 512, 58240>>>(Wg0, bg0, Wg1, bg1, Wout, bout, OUT);
}

// round 7
// speedup vs baseline: 1.1371x; 1.1371x over previous
#include <cuda_runtime.h>
#include <math.h>

#define BATCH 2
#define TLEN  2048
#define DIM   256
#define CD    64
#define TC    512
#define SEQ   (TC + TLEN)
#define KTOP  8

static __device__ __forceinline__ float fneginf() { return __int_as_float(0xff800000); }

// ----------------------------- scratch ------------------------------------
__device__ float g_Q  [BATCH * TLEN * DIM];    // roped Q, [b][t][h*64+c]
__device__ float g_K  [BATCH * SEQ * CD];      // roped K over concat axis
__device__ float g_V  [BATCH * SEQ * CD];
__device__ float g_QI [BATCH * TLEN * 128];
__device__ float g_WIw[BATCH * TLEN * 4];
__device__ float g_KI [BATCH * TC * 32];
__device__ float g_cos[SEQ * 32];
__device__ float g_sin[SEQ * 32];

// ----------------------------- K0: rope tables -----------------------------
// inv_freq: fp64 pow, but only 32 per block (one warp). Trig: sincosf (f32,
// <=2ulp incl. accurate range reduction) -- ~1e-7 abs error vs fp64 path.
__global__ void k_tables()
{
    __shared__ float invf_s[32];
    const int tid = threadIdx.x;
    if (tid < 32)
        invf_s[tid] = (float)pow(10000.0, -(double)tid / 32.0);
    __syncthreads();
    int idx = blockIdx.x * 256 + tid;
    if (idx >= SEQ * 32) return;
    int pos = idx >> 5, j = idx & 31;
    float ang = (float)pos * invf_s[j];
    float s, c;
    sincosf(ang, &s, &c);
    g_cos[idx] = c;
    g_sin[idx] = s;
}

// ------------------ K1: fused token GEMMs + window compression -------------
__global__ __launch_bounds__(384) void k_pre(
    const float* __restrict__ H,
    const float* __restrict__ Wc_comp, const float* __restrict__ Wc_idx,
    const float* __restrict__ W_DQ, const float* __restrict__ W_IUQ,
    const float* __restrict__ W_w,  const float* __restrict__ W_Q,
    const float* __restrict__ W_KV,
    const float* __restrict__ gq, const float* __restrict__ gk,
    const float* __restrict__ gv)
{
    __shared__ float sm[11272];
    const int tid = threadIdx.x;

    if (blockIdx.x < 256) {
        // ======================= token path ================================
        float* h_s   = sm;          // [k][tok]  4096
        float* o_s   = sm + 4096;   // [tok][col] 6144
        float* rq_s  = sm + 10240;  // 64
        float* rkv_s = sm + 10304;  // 16
        const int b  = blockIdx.x >> 7;
        const int t0 = (blockIdx.x & 127) << 4;
        const float* Hb = H + ((size_t)b * TLEN + t0) * DIM;

        for (int i = tid; i < 16 * DIM; i += 384)
            h_s[(i & 255) * 16 + (i >> 8)] = Hb[i];
        __syncthreads();

        float acc[16];
#pragma unroll
        for (int i = 0; i < 16; i++) acc[i] = 0.f;
        const float* Wcol; int ldw;
        if (tid < 256)      { Wcol = W_Q  + tid;         ldw = 256; }
        else if (tid < 320) { Wcol = W_KV + (tid - 256); ldw = 64;  }
        else                { Wcol = W_DQ + (tid - 320); ldw = 64;  }
#pragma unroll 4
        for (int k = 0; k < DIM; k++) {
            float w = Wcol[(size_t)k * ldw];
            const float4* hr = (const float4*)(h_s + k * 16);
#pragma unroll
            for (int q = 0; q < 4; q++) {
                float4 a = hr[q];
                acc[4*q+0] += a.x * w; acc[4*q+1] += a.y * w;
                acc[4*q+2] += a.z * w; acc[4*q+3] += a.w * w;
            }
        }
#pragma unroll
        for (int tok = 0; tok < 16; tok++) o_s[tok * 384 + tid] = acc[tok];
        __syncthreads();

        if (tid < 64) {
            int tok = tid >> 2, h = tid & 3;
            float ss = 0.f;
            for (int c = 0; c < CD; c++) { float v = o_s[tok*384 + h*64 + c]; ss += v*v; }
            rq_s[tid] = rsqrtf(ss * (1.f/64.f) + 1e-6f);
        } else if (tid < 80) {
            int tok = tid - 64;
            float ss = 0.f;
            for (int c = 0; c < CD; c++) { float v = o_s[tok*384 + 256 + c]; ss += v*v; }
            rkv_s[tok] = rsqrtf(ss * (1.f/64.f) + 1e-6f);
        }
        __syncthreads();

        for (int i = tid; i < 16 * 256; i += 384) {
            int tok = i >> 8, cc = i & 255;
            int h = cc >> 6, c = cc & 63, j = c & 31;
            int t = t0 + tok;
            float r = rq_s[tok * 4 + h];
            float x1 = o_s[tok*384 + h*64 + j]      * r * gq[h*64 + j];
            float x2 = o_s[tok*384 + h*64 + j + 32] * r * gq[h*64 + j + 32];
            float cs = g_cos[t*32 + j], sn = g_sin[t*32 + j];
            g_Q[((size_t)b*TLEN + t) * 256 + cc] = (c < 32) ? (x1*cs - x2*sn)
                                                            : (x1*sn + x2*cs);
        }
        for (int i = tid; i < 16 * 64; i += 384) {
            int tok = i >> 6, c = i & 63, j = c & 31;
            int t = t0 + tok, pos = TC + t;
            float r = rkv_s[tok];
            float x1 = o_s[tok*384 + 256 + j]      * r;
            float x2 = o_s[tok*384 + 256 + j + 32] * r;
            float cs = g_cos[pos*32 + j], sn = g_sin[pos*32 + j];
            float k1 = x1*gk[j], k2 = x2*gk[j+32];
            float v1 = x1*gv[j], v2 = x2*gv[j+32];
            size_t o = ((size_t)b*SEQ + pos) * 64 + c;
            g_K[o] = (c < 32) ? (k1*cs - k2*sn) : (k1*sn + k2*cs);
            g_V[o] = (c < 32) ? (v1*cs - v2*sn) : (v1*sn + v2*cs);
        }
        for (int i = tid; i < 16 * 128; i += 384) {
            int tok = i >> 7, c = i & 127;
            const float* hd = &o_s[tok*384 + 320];
            float a = 0.f;
#pragma unroll 4
            for (int k = 0; k < 64; k++) a += hd[k] * W_IUQ[k*128 + c];
            g_QI[((size_t)b*TLEN + t0 + tok) * 128 + c] = a;
        }
        if (tid < 64) {
            int tok = tid >> 2, c = tid & 3;
            const float* hd = &o_s[tok*384 + 320];
            float a = 0.f;
            for (int k = 0; k < 64; k++) a += hd[k] * W_w[k*4 + c];
            g_WIw[((size_t)b*TLEN + t0 + tok) * 4 + c] = a;
        }
    } else {
        // ======================= compress path =============================
        float* win    = sm;          // 9216
        float* comp_s = sm + 9216;   // 512
        float* red_s  = sm + 9728;   // 1536
        float* rms_s  = sm + 11264;  // 8
        const int cb = blockIdx.x - 256;
        const int b  = cb >> 6;
        const int s0 = (cb & 63) << 3;
        const int row0 = s0 << 2;

        for (int i = tid; i < 36 * DIM; i += 384) {
            int r = row0 + (i >> 8);
            win[i] = (r < TLEN) ? H[((size_t)b*TLEN + r) * DIM + (i & 255)] : 0.f;
        }
        __syncthreads();

        const int col = tid % 96;
        const int sub = tid / 96;
        const int grp = sub >> 1;
        const int kh  = sub & 1;
        const int ds0 = grp << 2;
        const float* Wcol; int ldw;
        if (col < 64) { Wcol = Wc_comp + col;       ldw = 64; }
        else          { Wcol = Wc_idx + (col - 64); ldw = 32; }

        float a0 = 0.f, a1 = 0.f, a2 = 0.f, a3 = 0.f;
        const int k4b = kh << 8;
        for (int k4 = k4b; k4 < k4b + 256; k4++) {
            float w0 = Wcol[(size_t)(4*k4+0) * ldw];
            float w1 = Wcol[(size_t)(4*k4+1) * ldw];
            float w2 = Wcol[(size_t)(4*k4+2) * ldw];
            float w3 = Wcol[(size_t)(4*k4+3) * ldw];
            int lrow = k4 >> 6;
            int coff = (k4 & 63) << 2;
#pragma unroll
            for (int d = 0; d < 4; d++) {
                const float4 wv = *(const float4*)&win[(4*(ds0+d) + lrow) * DIM + coff];
                float s = wv.x*w0 + wv.y*w1 + wv.z*w2 + wv.w*w3;
                if (d == 0) a0 += s; else if (d == 1) a1 += s;
                else if (d == 2) a2 += s; else a3 += s;
            }
        }
        *(float4*)&red_s[(sub*96 + col) * 4] = make_float4(a0, a1, a2, a3);
        __syncthreads();
        if (kh == 0) {
            float4 mine = *(const float4*)&red_s[(sub*96 + col) * 4];
            float4 othr = *(const float4*)&red_s[((sub+1)*96 + col) * 4];
            float av[4] = { mine.x + othr.x, mine.y + othr.y,
                            mine.z + othr.z, mine.w + othr.w };
#pragma unroll
            for (int d = 0; d < 4; d++) {
                int ds = ds0 + d;
                if (col < 64) comp_s[ds*64 + col] = av[d];
                else g_KI[((size_t)b*TC + s0 + ds) * 32 + (col - 64)] = av[d];
            }
        }
        __syncthreads();
        if (tid < 8) {
            float ss = 0.f;
            for (int c = 0; c < 64; c++) { float v = comp_s[tid*64 + c]; ss += v*v; }
            rms_s[tid] = rsqrtf(ss * (1.f/64.f) + 1e-6f);
        }
        __syncthreads();
        for (int i = tid; i < 8 * 64; i += 384) {
            int ds = i >> 6, c = i & 63, j = c & 31;
            int pos = s0 + ds;
            float r = rms_s[ds];
            float x1 = comp_s[ds*64 + j] * r, x2 = comp_s[ds*64 + j + 32] * r;
            float cs = g_cos[pos*32 + j], sn = g_sin[pos*32 + j];
            float k1 = x1*gk[j], k2 = x2*gk[j+32];
            float v1 = x1*gv[j], v2 = x2*gv[j+32];
            size_t o = ((size_t)b*SEQ + pos) * 64 + c;
            g_K[o] = (c < 32) ? (k1*cs - k2*sn) : (k1*sn + k2*cs);
            g_V[o] = (c < 32) ? (v1*cs - v2*sn) : (v1*sn + v2*cs);
        }
    }
}

// ------------------ K2: fused scores + topk + attention + projections ------
#define ISTRIDE 514
#define KVPAD   68
static __device__ __forceinline__ unsigned long long packkey(float v, int s)
{
    unsigned u = __float_as_uint(v);
    u = (u & 0x80000000u) ? ~u : (u | 0x80000000u);
    return ((unsigned long long)u << 32) | (unsigned)(511 - s);
}

__global__ __launch_bounds__(512) void k_main(
    const float* __restrict__ Wg0, const float* __restrict__ bg0,
    const float* __restrict__ Wg1, const float* __restrict__ bg1,
    const float* __restrict__ Wout, const float* __restrict__ bout,
    float* __restrict__ OUT)
{
    extern __shared__ float dsm[];
    float* qi_s = dsm;
    float* ki_s = dsm + 2112;
    float* i_s  = dsm + 6208;
    float* qo_s = dsm;
    float* kK_s = dsm + 4096;
    float* vV_s = dsm + 6208;
    float* g_s  = dsm + 8320;
    float* p_s  = dsm + 10368;
    int*   top_s = (int*)(dsm + 14432);

    const int tid = threadIdx.x;
    const int b  = blockIdx.x >> 7;
    const int r  = blockIdx.x & 127;
    const int t0 = (127 - r) << 4;                 // heavy blocks first
    const int nchunk = ((((t0 + 15) >> 2) + 1) + 127) >> 7;

    // ---------------- phase 1: index scores ----------------
    for (int i = tid; i < 16 * 128; i += 512)
        qi_s[(i >> 7) * 132 + (i & 127)] =
            g_QI[((size_t)b*TLEN + t0 + (i >> 7)) * 128 + (i & 127)];

    const int tok  = tid & 15;
    const int sgrp = tid >> 4;                     // 0..31, 4 s-values each
    const float4 wIw = *(const float4*)&g_WIw[((size_t)b*TLEN + t0 + tok) * 4];

    for (int c = 0; c < nchunk; c++) {
        const int s0 = c << 7;
        __syncthreads();
        for (int i = tid; i < 128 * 32; i += 512)
            ki_s[i] = g_KI[((size_t)b*TC + s0) * 32 + i];
        __syncthreads();

        float acc[4][4];
#pragma unroll
        for (int h = 0; h < 4; h++)
#pragma unroll
            for (int j = 0; j < 4; j++) acc[h][j] = 0.f;
#pragma unroll
        for (int c4 = 0; c4 < 8; c4++) {
            float4 q4[4];
#pragma unroll
            for (int h = 0; h < 4; h++)
                q4[h] = *(const float4*)&qi_s[tok*132 + h*32 + c4*4];
#pragma unroll
            for (int j = 0; j < 4; j++) {
                const float4 kv = *(const float4*)&ki_s[(sgrp*4 + j)*32 + c4*4];
#pragma unroll
                for (int h = 0; h < 4; h++)
                    acc[h][j] += q4[h].x*kv.x + q4[h].y*kv.y + q4[h].z*kv.z + q4[h].w*kv.w;
            }
        }
#pragma unroll
        for (int j = 0; j < 4; j++) {
            float v = wIw.x*fmaxf(acc[0][j],0.f) + wIw.y*fmaxf(acc[1][j],0.f)
                    + wIw.z*fmaxf(acc[2][j],0.f) + wIw.w*fmaxf(acc[3][j],0.f);
            i_s[tok*ISTRIDE + s0 + sgrp*4 + j] = v;
        }
    }
    __syncthreads();

    // ---------------- phase 2a: stage qo + sliding K, and top-k ----------
    for (int i = tid; i < 16 * 256; i += 512)
        qo_s[i] = g_Q[((size_t)b*TLEN + t0) * 256 + i];
    for (int i = tid; i < 31 * 64; i += 512) {
        int rel = i >> 6, c = i & 63;
        int row = TC + t0 - 15 + rel;
        kK_s[rel*KVPAD + c] = (row >= TC) ? g_K[((size_t)b*SEQ + row)*64 + c] : 0.f;
    }
    {   // top-k: warp w -> token t0+w (exact jax.lax.top_k semantics)
        const int w = tid >> 5, l = tid & 31;
        const int t = t0 + w;
        const float* Irow = &i_s[w * ISTRIDE];
        unsigned long long keys[16];
#pragma unroll
        for (int k = 0; k < 16; k++) {
            int s = l + 32*k;
            float v = (4*s <= t) ? Irow[s] : fneginf();
            keys[k] = packkey(v, s);
        }
#pragma unroll 1
        for (int i = 0; i < KTOP; i++) {
            unsigned long long best = 0ull;
#pragma unroll
            for (int k = 0; k < 16; k++) best = max(best, keys[k]);
#pragma unroll
            for (int off = 16; off; off >>= 1)
                best = max(best, __shfl_xor_sync(0xffffffffu, best, off));
            int s_win = 511 - (int)(best & 0xffffffffull);
            if (l == 0) top_s[w*8 + i] = s_win;
            if ((s_win & 31) == l) keys[s_win >> 5] = 0ull;
        }
    }
    __syncthreads();

    // ---------------- phase 2b: stage sliding V (overwrites i_s) ----------
    for (int i = tid; i < 31 * 64; i += 512) {
        int rel = i >> 6, c = i & 63;
        int row = TC + t0 - 15 + rel;
        vV_s[rel*KVPAD + c] = (row >= TC) ? g_V[((size_t)b*SEQ + row)*64 + c] : 0.f;
    }
    __syncthreads();

    // ---------------- phase 3: attention ----------------
    {
        const int w = tid >> 5, l = tid & 31;
        const int t = t0 + w;
        const int nsl = (t + 1 < 16) ? (t + 1) : 16;
        const int nkey = 8 + nsl;

        float dh[4] = {0.f, 0.f, 0.f, 0.f};
        bool valid = false;
        if (l < 8) {
            valid = true;
            int row = top_s[w*8 + l];
            const float4* kp = (const float4*)(g_K + ((size_t)b*SEQ + row) * 64);
#pragma unroll
            for (int c4 = 0; c4 < 16; c4++) {
                float4 kv = kp[c4];
#pragma unroll
                for (int h = 0; h < 4; h++) {
                    float4 q4 = *(const float4*)&qo_s[w*256 + h*64 + c4*4];
                    dh[h] += q4.x*kv.x + q4.y*kv.y + q4.z*kv.z + q4.w*kv.w;
                }
            }
        } else if (l < 24) {
            valid = (l < nkey);
            const float4* kp = (const float4*)(kK_s + (w + 23 - l) * KVPAD);
#pragma unroll
            for (int c4 = 0; c4 < 16; c4++) {
                float4 kv = kp[c4];
#pragma unroll
                for (int h = 0; h < 4; h++) {
                    float4 q4 = *(const float4*)&qo_s[w*256 + h*64 + c4*4];
                    dh[h] += q4.x*kv.x + q4.y*kv.y + q4.z*kv.z + q4.w*kv.w;
                }
            }
        }
#pragma unroll
        for (int h = 0; h < 4; h++) {
            float s = valid ? dh[h] * 0.125f : fneginf();
            float m = s;
#pragma unroll
            for (int off = 16; off; off >>= 1)
                m = fmaxf(m, __shfl_xor_sync(0xffffffffu, m, off));
            float e = expf(s - m);
            float sum = e;
#pragma unroll
            for (int off = 16; off; off >>= 1)
                sum += __shfl_xor_sync(0xffffffffu, sum, off);
            float p = e / sum;                 // 0 for invalid lanes
            if (l < 24) p_s[w*96 + h*24 + l] = p;
        }
        __syncwarp();

        float o1[4] = {0,0,0,0}, o2[4] = {0,0,0,0};
#pragma unroll
        for (int j = 0; j < 8; j++) {          // top-k keys: gmem gather
            int rj = top_s[w*8 + j];
            const float* vp = g_V + ((size_t)b*SEQ + rj) * 64;
            float v1 = vp[l], v2 = vp[l + 32];
#pragma unroll
            for (int h = 0; h < 4; h++) {
                float p = p_s[w*96 + h*24 + j];
                o1[h] += p * v1;
                o2[h] += p * v2;
            }
        }
#pragma unroll
        for (int j = 8; j < 24; j++) {         // sliding keys: smem
            const float* vp = vV_s + (w + 23 - j) * KVPAD;
            float v1 = vp[l], v2 = vp[l + 32];
#pragma unroll
            for (int h = 0; h < 4; h++) {
                float p = p_s[w*96 + h*24 + j];
                o1[h] += p * v1;
                o2[h] += p * v2;
            }
        }
        float cs = g_cos[t*32 + l], sn = g_sin[t*32 + l];
        __syncwarp();   // all lanes done reading qo_s[w] before overwrite
#pragma unroll
        for (int h = 0; h < 4; h++) {
            qo_s[w*256 + h*64 + l]      =  o1[h]*cs + o2[h]*sn;
            qo_s[w*256 + h*64 + 32 + l] = -o1[h]*sn + o2[h]*cs;
        }
    }
    __syncthreads();

    // ---------------- phase 4: gate projections ----------------
    {
        const int col = tid & 127;
        const int tq  = tid >> 7;               // 4 tokens each
        const int c   = col & 63;
        const float* Wg = (col < 64) ? Wg0 : Wg1;
        const float  bb = (col < 64) ? bg0[c] : bg1[c];
        const int obase = (col < 64) ? 0 : 128;
        float a[4] = {bb, bb, bb, bb};
#pragma unroll 4
        for (int k = 0; k < 128; k++) {
            float wv = Wg[k*64 + c];
#pragma unroll
            for (int u = 0; u < 4; u++)
                a[u] += qo_s[(tq*4 + u)*256 + obase + k] * wv;
        }
#pragma unroll
        for (int u = 0; u < 4; u++) g_s[(tq*4 + u)*128 + col] = a[u];
    }
    __syncthreads();

    // ---------------- phase 5: final projection ----------------
    {
        const int col = tid & 255;
        const int tq  = tid >> 8;               // 8 tokens each
        float bb = bout[col];
        float a[8] = {bb, bb, bb, bb, bb, bb, bb, bb};
#pragma unroll 4
        for (int k = 0; k < 128; k++) {
            float wv = Wout[k*256 + col];
#pragma unroll
            for (int u = 0; u < 8; u++)
                a[u] += g_s[(tq*8 + u)*128 + k] * wv;
        }
#pragma unroll
        for (int u = 0; u < 8; u++)
            OUT[((size_t)b*TLEN + t0 + tq*8 + u) * DIM + col] = a[u];
    }
}

// ----------------------------- launcher ------------------------------------
extern "C" void kernel_launch(void* const* d_in, const int* in_sizes, int n_in,
                              void* d_out, int out_size)
{
    const float* H       = (const float*)d_in[0];
    const float* Wc_comp = (const float*)d_in[1];
    const float* Wc_idx  = (const float*)d_in[2];
    const float* W_DQ    = (const float*)d_in[3];
    const float* W_IUQ   = (const float*)d_in[4];
    const float* W_w     = (const float*)d_in[5];
    const float* W_Q     = (const float*)d_in[6];
    const float* W_KV    = (const float*)d_in[7];
    const float* gq      = (const float*)d_in[8];
    const float* gk      = (const float*)d_in[9];
    const float* gv      = (const float*)d_in[10];
    const float* Wg0     = (const float*)d_in[11];
    const float* bg0     = (const float*)d_in[12];
    const float* Wg1     = (const float*)d_in[13];
    const float* bg1     = (const float*)d_in[14];
    const float* Wout    = (const float*)d_in[15];
    const float* bout    = (const float*)d_in[16];
    float* OUT = (float*)d_out;

    static int smem_set = 0;
    if (!smem_set) {
        cudaFuncSetAttribute(k_main,
                             cudaFuncAttributeMaxDynamicSharedMemorySize, 58240);
        smem_set = 1;
    }

    k_tables<<<(SEQ * 32 + 255) / 256, 256>>>();
    k_pre<<<256 + 128, 384>>>(H, Wc_comp, Wc_idx, W_DQ, W_IUQ, W_w, W_Q, W_KV,
                              gq, gk, gv);
    k_main<<<BATCH * 128, 512, 58240>>>(Wg0, bg0, Wg1, bg1, Wout, bout, OUT);
}

// round 14
// speedup vs baseline: 1.1628x; 1.0226x over previous
#include <cuda_runtime.h>
#include <math.h>

#define BATCH 2
#define TLEN  2048
#define DIM   256
#define CD    64
#define TC    512
#define SEQ   (TC + TLEN)
#define KTOP  8

static __device__ __forceinline__ float fneginf() { return __int_as_float(0xff800000); }

// ----------------------------- scratch ------------------------------------
__device__ float g_Q  [BATCH * TLEN * DIM];    // roped Q, [b][t][h*64+c]
__device__ float g_K  [BATCH * SEQ * CD];      // roped K over concat axis
__device__ float g_V  [BATCH * SEQ * CD];
__device__ float g_QI [BATCH * TLEN * 128];
__device__ float g_WIw[BATCH * TLEN * 4];
__device__ float g_KI [BATCH * TC * 32];

// ------------------ K1: fused token GEMMs + window compression -------------
// blocks [0,256): token path — 16 tokens/block, 384 threads.
// blocks [256,384): compress — 8 windows/block, 2 grp x 2 ksplit.
// RoPE trig inline: per-block fp64-pow inv_freq (32 lanes) + sincosf.
__global__ __launch_bounds__(384) void k_pre(
    const float* __restrict__ H,
    const float* __restrict__ Wc_comp, const float* __restrict__ Wc_idx,
    const float* __restrict__ W_DQ, const float* __restrict__ W_IUQ,
    const float* __restrict__ W_w,  const float* __restrict__ W_Q,
    const float* __restrict__ W_KV,
    const float* __restrict__ gq, const float* __restrict__ gk,
    const float* __restrict__ gv)
{
    __shared__ float sm[11304];
    float* invf_s = sm + 11272;
    const int tid = threadIdx.x;

    if (tid < 32)
        invf_s[tid] = (float)pow(10000.0, -(double)tid / 32.0);

    if (blockIdx.x < 256) {
        // ======================= token path ================================
        float* h_s   = sm;          // [k][tok]  4096
        float* o_s   = sm + 4096;   // [tok][col] 6144
        float* rq_s  = sm + 10240;  // 64
        float* rkv_s = sm + 10304;  // 16
        const int b  = blockIdx.x >> 7;
        const int t0 = (blockIdx.x & 127) << 4;
        const float* Hb = H + ((size_t)b * TLEN + t0) * DIM;

        for (int i = tid; i < 16 * DIM; i += 384)
            h_s[(i & 255) * 16 + (i >> 8)] = Hb[i];
        __syncthreads();

        float acc[16];
#pragma unroll
        for (int i = 0; i < 16; i++) acc[i] = 0.f;
        const float* Wcol; int ldw;
        if (tid < 256)      { Wcol = W_Q  + tid;         ldw = 256; }
        else if (tid < 320) { Wcol = W_KV + (tid - 256); ldw = 64;  }
        else                { Wcol = W_DQ + (tid - 320); ldw = 64;  }
#pragma unroll 4
        for (int k = 0; k < DIM; k++) {
            float w = Wcol[(size_t)k * ldw];
            const float4* hr = (const float4*)(h_s + k * 16);
#pragma unroll
            for (int q = 0; q < 4; q++) {
                float4 a = hr[q];
                acc[4*q+0] += a.x * w; acc[4*q+1] += a.y * w;
                acc[4*q+2] += a.z * w; acc[4*q+3] += a.w * w;
            }
        }
#pragma unroll
        for (int tok = 0; tok < 16; tok++) o_s[tok * 384 + tid] = acc[tok];
        __syncthreads();

        if (tid < 64) {                       // Q rms per (tok, head)
            int tok = tid >> 2, h = tid & 3;
            float ss = 0.f;
            for (int c = 0; c < CD; c++) { float v = o_s[tok*384 + h*64 + c]; ss += v*v; }
            rq_s[tid] = rsqrtf(ss * (1.f/64.f) + 1e-6f);
        } else if (tid < 80) {                // KV rms per tok
            int tok = tid - 64;
            float ss = 0.f;
            for (int c = 0; c < CD; c++) { float v = o_s[tok*384 + 256 + c]; ss += v*v; }
            rkv_s[tok] = rsqrtf(ss * (1.f/64.f) + 1e-6f);
        }
        __syncthreads();

        // Q rope: one sincosf per (tok, j) covers all 4 heads + both halves
        for (int i = tid; i < 16 * 32; i += 384) {
            int tok = i >> 5, j = i & 31;
            int t = t0 + tok;
            float sn, cs;
            sincosf((float)t * invf_s[j], &sn, &cs);
            const float* orow = &o_s[tok*384];
            size_t qbase = ((size_t)b*TLEN + t) * 256;
#pragma unroll
            for (int h = 0; h < 4; h++) {
                float r = rq_s[tok*4 + h];
                float x1 = orow[h*64 + j]      * r * gq[h*64 + j];
                float x2 = orow[h*64 + j + 32] * r * gq[h*64 + j + 32];
                g_Q[qbase + h*64 + j]      = x1*cs - x2*sn;
                g_Q[qbase + h*64 + j + 32] = x1*sn + x2*cs;
            }
        }
        // sliding K/V rope at pos TC + t
        for (int i = tid; i < 16 * 32; i += 384) {
            int tok = i >> 5, j = i & 31;
            int t = t0 + tok, pos = TC + t;
            float sn, cs;
            sincosf((float)pos * invf_s[j], &sn, &cs);
            float r = rkv_s[tok];
            float x1 = o_s[tok*384 + 256 + j]      * r;
            float x2 = o_s[tok*384 + 256 + j + 32] * r;
            float k1 = x1*gk[j], k2 = x2*gk[j+32];
            float v1 = x1*gv[j], v2 = x2*gv[j+32];
            size_t o = ((size_t)b*SEQ + pos) * 64;
            g_K[o + j]      = k1*cs - k2*sn;
            g_K[o + j + 32] = k1*sn + k2*cs;
            g_V[o + j]      = v1*cs - v2*sn;
            g_V[o + j + 32] = v1*sn + v2*cs;
        }
        // Q_I = H_dc @ W_IUQ  (H_dc = cols 320..383)
        for (int i = tid; i < 16 * 128; i += 384) {
            int tok = i >> 7, c = i & 127;
            const float* hd = &o_s[tok*384 + 320];
            float a = 0.f;
#pragma unroll 4
            for (int k = 0; k < 64; k++) a += hd[k] * W_IUQ[k*128 + c];
            g_QI[((size_t)b*TLEN + t0 + tok) * 128 + c] = a;
        }
        if (tid < 64) {                        // W_Iw = H_dc @ W_w
            int tok = tid >> 2, c = tid & 3;
            const float* hd = &o_s[tok*384 + 320];
            float a = 0.f;
            for (int k = 0; k < 64; k++) a += hd[k] * W_w[k*4 + c];
            g_WIw[((size_t)b*TLEN + t0 + tok) * 4 + c] = a;
        }
    } else {
        // ======================= compress path =============================
        float* win    = sm;          // 9216
        float* comp_s = sm + 9216;   // 512
        float* red_s  = sm + 9728;   // 1536
        float* rms_s  = sm + 11264;  // 8
        const int cb = blockIdx.x - 256;
        const int b  = cb >> 6;
        const int s0 = (cb & 63) << 3;
        const int row0 = s0 << 2;

        for (int i = tid; i < 36 * DIM; i += 384) {
            int r = row0 + (i >> 8);
            win[i] = (r < TLEN) ? H[((size_t)b*TLEN + r) * DIM + (i & 255)] : 0.f;
        }
        __syncthreads();

        const int col = tid % 96;
        const int sub = tid / 96;
        const int grp = sub >> 1;
        const int kh  = sub & 1;
        const int ds0 = grp << 2;
        const float* Wcol; int ldw;
        if (col < 64) { Wcol = Wc_comp + col;       ldw = 64; }
        else          { Wcol = Wc_idx + (col - 64); ldw = 32; }

        float a0 = 0.f, a1 = 0.f, a2 = 0.f, a3 = 0.f;
        const int k4b = kh << 8;
        for (int k4 = k4b; k4 < k4b + 256; k4++) {
            float w0 = Wcol[(size_t)(4*k4+0) * ldw];
            float w1 = Wcol[(size_t)(4*k4+1) * ldw];
            float w2 = Wcol[(size_t)(4*k4+2) * ldw];
            float w3 = Wcol[(size_t)(4*k4+3) * ldw];
            int lrow = k4 >> 6;
            int coff = (k4 & 63) << 2;
#pragma unroll
            for (int d = 0; d < 4; d++) {
                const float4 wv = *(const float4*)&win[(4*(ds0+d) + lrow) * DIM + coff];
                float s = wv.x*w0 + wv.y*w1 + wv.z*w2 + wv.w*w3;
                if (d == 0) a0 += s; else if (d == 1) a1 += s;
                else if (d == 2) a2 += s; else a3 += s;
            }
        }
        *(float4*)&red_s[(sub*96 + col) * 4] = make_float4(a0, a1, a2, a3);
        __syncthreads();
        if (kh == 0) {
            float4 mine = *(const float4*)&red_s[(sub*96 + col) * 4];
            float4 othr = *(const float4*)&red_s[((sub+1)*96 + col) * 4];
            float av[4] = { mine.x + othr.x, mine.y + othr.y,
                            mine.z + othr.z, mine.w + othr.w };
#pragma unroll
            for (int d = 0; d < 4; d++) {
                int ds = ds0 + d;
                if (col < 64) comp_s[ds*64 + col] = av[d];
                else g_KI[((size_t)b*TC + s0 + ds) * 32 + (col - 64)] = av[d];
            }
        }
        __syncthreads();
        if (tid < 8) {
            float ss = 0.f;
            for (int c = 0; c < 64; c++) { float v = comp_s[tid*64 + c]; ss += v*v; }
            rms_s[tid] = rsqrtf(ss * (1.f/64.f) + 1e-6f);
        }
        __syncthreads();
        for (int i = tid; i < 8 * 32; i += 384) {
            int ds = i >> 5, j = i & 31;
            int pos = s0 + ds;
            float sn, cs;
            sincosf((float)pos * invf_s[j], &sn, &cs);
            float r = rms_s[ds];
            float x1 = comp_s[ds*64 + j] * r, x2 = comp_s[ds*64 + j + 32] * r;
            float k1 = x1*gk[j], k2 = x2*gk[j+32];
            float v1 = x1*gv[j], v2 = x2*gv[j+32];
            size_t o = ((size_t)b*SEQ + pos) * 64;
            g_K[o + j]      = k1*cs - k2*sn;
            g_K[o + j + 32] = k1*sn + k2*cs;
            g_V[o + j]      = v1*cs - v2*sn;
            g_V[o + j + 32] = v1*sn + v2*cs;
        }
    }
}

// ------------------ K2: fused scores + topk + attention + projections ------
// phase-1 smem (floats): qi[0,2112) ki[2112,6208) i_s[6208,14432)
// phase-2 smem:          qo[0,4096) kK[4096,6204) vV[6208,8316)
//                        g_s[8320,10368) p_s[10368,11904)
// persistent:            top_s (ints) at [14432,14560)
#define ISTRIDE 514
#define KVPAD   68
static __device__ __forceinline__ unsigned long long packkey(float v, int s)
{
    unsigned u = __float_as_uint(v);
    u = (u & 0x80000000u) ? ~u : (u | 0x80000000u);
    return ((unsigned long long)u << 32) | (unsigned)(511 - s);
}

__global__ __launch_bounds__(512) void k_main(
    const float* __restrict__ Wg0, const float* __restrict__ bg0,
    const float* __restrict__ Wg1, const float* __restrict__ bg1,
    const float* __restrict__ Wout, const float* __restrict__ bout,
    float* __restrict__ OUT)
{
    extern __shared__ float dsm[];
    __shared__ float invf_s[32];
    float* qi_s = dsm;
    float* ki_s = dsm + 2112;
    float* i_s  = dsm + 6208;
    float* qo_s = dsm;
    float* kK_s = dsm + 4096;
    float* vV_s = dsm + 6208;
    float* g_s  = dsm + 8320;
    float* p_s  = dsm + 10368;
    int*   top_s = (int*)(dsm + 14432);

    const int tid = threadIdx.x;
    const int b  = blockIdx.x >> 7;
    const int r  = blockIdx.x & 127;
    const int t0 = (127 - r) << 4;                 // heavy blocks first
    const int nchunk = ((((t0 + 15) >> 2) + 1) + 127) >> 7;

    if (tid < 32)
        invf_s[tid] = (float)pow(10000.0, -(double)tid / 32.0);

    // ---------------- phase 1: index scores ----------------
    for (int i = tid; i < 16 * 128; i += 512)
        qi_s[(i >> 7) * 132 + (i & 127)] =
            g_QI[((size_t)b*TLEN + t0 + (i >> 7)) * 128 + (i & 127)];

    const int tok  = tid & 15;
    const int sgrp = tid >> 4;                     // 0..31, 4 s-values each
    const float4 wIw = *(const float4*)&g_WIw[((size_t)b*TLEN + t0 + tok) * 4];

    for (int c = 0; c < nchunk; c++) {
        const int s0 = c << 7;
        __syncthreads();
        for (int i = tid; i < 128 * 32; i += 512)
            ki_s[i] = g_KI[((size_t)b*TC + s0) * 32 + i];
        __syncthreads();

        float acc[4][4];
#pragma unroll
        for (int h = 0; h < 4; h++)
#pragma unroll
            for (int j = 0; j < 4; j++) acc[h][j] = 0.f;
#pragma unroll
        for (int c4 = 0; c4 < 8; c4++) {
            float4 q4[4];
#pragma unroll
            for (int h = 0; h < 4; h++)
                q4[h] = *(const float4*)&qi_s[tok*132 + h*32 + c4*4];
#pragma unroll
            for (int j = 0; j < 4; j++) {
                const float4 kv = *(const float4*)&ki_s[(sgrp*4 + j)*32 + c4*4];
#pragma unroll
                for (int h = 0; h < 4; h++)
                    acc[h][j] += q4[h].x*kv.x + q4[h].y*kv.y + q4[h].z*kv.z + q4[h].w*kv.w;
            }
        }
#pragma unroll
        for (int j = 0; j < 4; j++) {
            float v = wIw.x*fmaxf(acc[0][j],0.f) + wIw.y*fmaxf(acc[1][j],0.f)
                    + wIw.z*fmaxf(acc[2][j],0.f) + wIw.w*fmaxf(acc[3][j],0.f);
            i_s[tok*ISTRIDE + s0 + sgrp*4 + j] = v;
        }
    }
    __syncthreads();

    // ---------------- phase 2a: stage qo + sliding K, and top-k ----------
    for (int i = tid; i < 16 * 256; i += 512)
        qo_s[i] = g_Q[((size_t)b*TLEN + t0) * 256 + i];
    for (int i = tid; i < 31 * 64; i += 512) {
        int rel = i >> 6, c = i & 63;
        int row = TC + t0 - 15 + rel;
        kK_s[rel*KVPAD + c] = (row >= TC) ? g_K[((size_t)b*SEQ + row)*64 + c] : 0.f;
    }
    {   // top-k: warp w -> token t0+w (exact jax.lax.top_k semantics)
        const int w = tid >> 5, l = tid & 31;
        const int t = t0 + w;
        const float* Irow = &i_s[w * ISTRIDE];
        unsigned long long keys[16];
#pragma unroll
        for (int k = 0; k < 16; k++) {
            int s = l + 32*k;
            float v = (4*s <= t) ? Irow[s] : fneginf();
            keys[k] = packkey(v, s);
        }
#pragma unroll 1
        for (int i = 0; i < KTOP; i++) {
            unsigned long long best = 0ull;
#pragma unroll
            for (int k = 0; k < 16; k++) best = max(best, keys[k]);
#pragma unroll
            for (int off = 16; off; off >>= 1)
                best = max(best, __shfl_xor_sync(0xffffffffu, best, off));
            int s_win = 511 - (int)(best & 0xffffffffull);
            if (l == 0) top_s[w*8 + i] = s_win;
            if ((s_win & 31) == l) keys[s_win >> 5] = 0ull;
        }
    }
    __syncthreads();

    // ---------------- phase 2b: stage sliding V (overwrites i_s) ----------
    for (int i = tid; i < 31 * 64; i += 512) {
        int rel = i >> 6, c = i & 63;
        int row = TC + t0 - 15 + rel;
        vV_s[rel*KVPAD + c] = (row >= TC) ? g_V[((size_t)b*SEQ + row)*64 + c] : 0.f;
    }
    __syncthreads();

    // ---------------- phase 3: attention ----------------
    {
        const int w = tid >> 5, l = tid & 31;
        const int t = t0 + w;
        const int nsl = (t + 1 < 16) ? (t + 1) : 16;
        const int nkey = 8 + nsl;

        float dh[4] = {0.f, 0.f, 0.f, 0.f};
        bool valid = false;
        if (l < 8) {
            valid = true;
            int row = top_s[w*8 + l];
            const float4* kp = (const float4*)(g_K + ((size_t)b*SEQ + row) * 64);
#pragma unroll
            for (int c4 = 0; c4 < 16; c4++) {
                float4 kv = kp[c4];
#pragma unroll
                for (int h = 0; h < 4; h++) {
                    float4 q4 = *(const float4*)&qo_s[w*256 + h*64 + c4*4];
                    dh[h] += q4.x*kv.x + q4.y*kv.y + q4.z*kv.z + q4.w*kv.w;
                }
            }
        } else if (l < 24) {
            valid = (l < nkey);
            const float4* kp = (const float4*)(kK_s + (w + 23 - l) * KVPAD);
#pragma unroll
            for (int c4 = 0; c4 < 16; c4++) {
                float4 kv = kp[c4];
#pragma unroll
                for (int h = 0; h < 4; h++) {
                    float4 q4 = *(const float4*)&qo_s[w*256 + h*64 + c4*4];
                    dh[h] += q4.x*kv.x + q4.y*kv.y + q4.z*kv.z + q4.w*kv.w;
                }
            }
        }
#pragma unroll
        for (int h = 0; h < 4; h++) {
            float s = valid ? dh[h] * 0.125f : fneginf();
            float m = s;
#pragma unroll
            for (int off = 16; off; off >>= 1)
                m = fmaxf(m, __shfl_xor_sync(0xffffffffu, m, off));
            float e = expf(s - m);
            float sum = e;
#pragma unroll
            for (int off = 16; off; off >>= 1)
                sum += __shfl_xor_sync(0xffffffffu, sum, off);
            float p = e / sum;                 // 0 for invalid lanes
            if (l < 24) p_s[w*96 + h*24 + l] = p;
        }
        __syncwarp();

        float o1[4] = {0,0,0,0}, o2[4] = {0,0,0,0};
#pragma unroll
        for (int j = 0; j < 8; j++) {          // top-k keys: gmem gather
            int rj = top_s[w*8 + j];
            const float* vp = g_V + ((size_t)b*SEQ + rj) * 64;
            float v1 = vp[l], v2 = vp[l + 32];
#pragma unroll
            for (int h = 0; h < 4; h++) {
                float p = p_s[w*96 + h*24 + j];
                o1[h] += p * v1;
                o2[h] += p * v2;
            }
        }
#pragma unroll
        for (int j = 8; j < 24; j++) {         // sliding keys: smem
            const float* vp = vV_s + (w + 23 - j) * KVPAD;
            float v1 = vp[l], v2 = vp[l + 32];
#pragma unroll
            for (int h = 0; h < 4; h++) {
                float p = p_s[w*96 + h*24 + j];
                o1[h] += p * v1;
                o2[h] += p * v2;
            }
        }
        float sn, cs;
        sincosf((float)t * invf_s[l], &sn, &cs);
        __syncwarp();   // all lanes done reading qo_s[w] before overwrite
#pragma unroll
        for (int h = 0; h < 4; h++) {
            qo_s[w*256 + h*64 + l]      =  o1[h]*cs + o2[h]*sn;
            qo_s[w*256 + h*64 + 32 + l] = -o1[h]*sn + o2[h]*cs;
        }
    }
    __syncthreads();

    // ---------------- phase 4: gate projections ----------------
    {
        const int col = tid & 127;
        const int tq  = tid >> 7;               // 4 tokens each
        const int c   = col & 63;
        const float* Wg = (col < 64) ? Wg0 : Wg1;
        const float  bb = (col < 64) ? bg0[c] : bg1[c];
        const int obase = (col < 64) ? 0 : 128;
        float a[4] = {bb, bb, bb, bb};
#pragma unroll 4
        for (int k = 0; k < 128; k++) {
            float wv = Wg[k*64 + c];
#pragma unroll
            for (int u = 0; u < 4; u++)
                a[u] += qo_s[(tq*4 + u)*256 + obase + k] * wv;
        }
#pragma unroll
        for (int u = 0; u < 4; u++) g_s[(tq*4 + u)*128 + col] = a[u];
    }
    __syncthreads();

    // ---------------- phase 5: final projection ----------------
    {
        const int col = tid & 255;
        const int tq  = tid >> 8;               // 8 tokens each
        float bb = bout[col];
        float a[8] = {bb, bb, bb, bb, bb, bb, bb, bb};
#pragma unroll 4
        for (int k = 0; k < 128; k++) {
            float wv = Wout[k*256 + col];
#pragma unroll
            for (int u = 0; u < 8; u++)
                a[u] += g_s[(tq*8 + u)*128 + k] * wv;
        }
#pragma unroll
        for (int u = 0; u < 8; u++)
            OUT[((size_t)b*TLEN + t0 + tq*8 + u) * DIM + col] = a[u];
    }
}

// ----------------------------- launcher ------------------------------------
extern "C" void kernel_launch(void* const* d_in, const int* in_sizes, int n_in,
                              void* d_out, int out_size)
{
    const float* H       = (const float*)d_in[0];
    const float* Wc_comp = (const float*)d_in[1];
    const float* Wc_idx  = (const float*)d_in[2];
    const float* W_DQ    = (const float*)d_in[3];
    const float* W_IUQ   = (const float*)d_in[4];
    const float* W_w     = (const float*)d_in[5];
    const float* W_Q     = (const float*)d_in[6];
    const float* W_KV    = (const float*)d_in[7];
    const float* gq      = (const float*)d_in[8];
    const float* gk      = (const float*)d_in[9];
    const float* gv      = (const float*)d_in[10];
    const float* Wg0     = (const float*)d_in[11];
    const float* bg0     = (const float*)d_in[12];
    const float* Wg1     = (const float*)d_in[13];
    const float* bg1     = (const float*)d_in[14];
    const float* Wout    = (const float*)d_in[15];
    const float* bout    = (const float*)d_in[16];
    float* OUT = (float*)d_out;

    cudaFuncSetAttribute(k_main,
                         cudaFuncAttributeMaxDynamicSharedMemorySize, 58240);

    k_pre<<<256 + 128, 384>>>(H, Wc_comp, Wc_idx, W_DQ, W_IUQ, W_w, W_Q, W_KV,
                              gq, gk, gv);
    k_main<<<BATCH * 128, 512, 58240>>>(Wg0, bg0, Wg1, bg1, Wout, bout, OUT);
}

// round 15
// speedup vs baseline: 1.2708x; 1.0928x over previous
#include <cuda_runtime.h>
#include <math.h>

#define BATCH 2
#define TLEN  2048
#define DIM   256
#define CD    64
#define TC    512
#define SEQ   (TC + TLEN)
#define KTOP  8

static __device__ __forceinline__ float fneginf() { return __int_as_float(0xff800000); }

// ----------------------------- scratch ------------------------------------
__device__ float g_Q  [BATCH * TLEN * DIM];    // roped Q, [b][t][h*64+c]
__device__ float g_K  [BATCH * SEQ * CD];      // roped K over concat axis
__device__ float g_V  [BATCH * SEQ * CD];
__device__ float g_QI [BATCH * TLEN * 128];
__device__ float g_WIw[BATCH * TLEN * 4];
__device__ float g_KI [BATCH * TC * 32];

// ------------------ K1: fused token GEMMs + window compression -------------
// blocks [0,256): token path — 16 tokens/block, 384 threads.
// blocks [256,384): compress — 8 windows/block, 2 grp x 2 ksplit.
// RoPE trig inline: per-block fp64-pow inv_freq (32 lanes) + sincosf.
__global__ __launch_bounds__(384, 3) void k_pre(
    const float* __restrict__ H,
    const float* __restrict__ Wc_comp, const float* __restrict__ Wc_idx,
    const float* __restrict__ W_DQ, const float* __restrict__ W_IUQ,
    const float* __restrict__ W_w,  const float* __restrict__ W_Q,
    const float* __restrict__ W_KV,
    const float* __restrict__ gq, const float* __restrict__ gk,
    const float* __restrict__ gv)
{
    __shared__ float sm[11304];
    float* invf_s = sm + 11272;
    const int tid = threadIdx.x;

    if (tid < 32)
        invf_s[tid] = (float)pow(10000.0, -(double)tid / 32.0);

    if (blockIdx.x < 256) {
        // ======================= token path ================================
        float* h_s   = sm;          // [k][tok]  4096
        float* o_s   = sm + 4096;   // [tok][col] 6144
        float* rq_s  = sm + 10240;  // 64
        float* rkv_s = sm + 10304;  // 16
        const int b  = blockIdx.x >> 7;
        const int t0 = (blockIdx.x & 127) << 4;
        const float* Hb = H + ((size_t)b * TLEN + t0) * DIM;

        for (int i = tid; i < 16 * DIM; i += 384)
            h_s[(i & 255) * 16 + (i >> 8)] = Hb[i];
        __syncthreads();

        float acc[16];
#pragma unroll
        for (int i = 0; i < 16; i++) acc[i] = 0.f;
        const float* Wcol; int ldw;
        if (tid < 256)      { Wcol = W_Q  + tid;         ldw = 256; }
        else if (tid < 320) { Wcol = W_KV + (tid - 256); ldw = 64;  }
        else                { Wcol = W_DQ + (tid - 320); ldw = 64;  }
#pragma unroll 4
        for (int k = 0; k < DIM; k++) {
            float w = Wcol[(size_t)k * ldw];
            const float4* hr = (const float4*)(h_s + k * 16);
#pragma unroll
            for (int q = 0; q < 4; q++) {
                float4 a = hr[q];
                acc[4*q+0] += a.x * w; acc[4*q+1] += a.y * w;
                acc[4*q+2] += a.z * w; acc[4*q+3] += a.w * w;
            }
        }
#pragma unroll
        for (int tok = 0; tok < 16; tok++) o_s[tok * 384 + tid] = acc[tok];
        __syncthreads();

        if (tid < 64) {                       // Q rms per (tok, head)
            int tok = tid >> 2, h = tid & 3;
            float ss = 0.f;
            for (int c = 0; c < CD; c++) { float v = o_s[tok*384 + h*64 + c]; ss += v*v; }
            rq_s[tid] = rsqrtf(ss * (1.f/64.f) + 1e-6f);
        } else if (tid < 80) {                // KV rms per tok
            int tok = tid - 64;
            float ss = 0.f;
            for (int c = 0; c < CD; c++) { float v = o_s[tok*384 + 256 + c]; ss += v*v; }
            rkv_s[tok] = rsqrtf(ss * (1.f/64.f) + 1e-6f);
        }
        __syncthreads();

        // Q rope: one sincosf per (tok, j) covers all 4 heads + both halves
        for (int i = tid; i < 16 * 32; i += 384) {
            int tok = i >> 5, j = i & 31;
            int t = t0 + tok;
            float sn, cs;
            sincosf((float)t * invf_s[j], &sn, &cs);
            const float* orow = &o_s[tok*384];
            size_t qbase = ((size_t)b*TLEN + t) * 256;
#pragma unroll
            for (int h = 0; h < 4; h++) {
                float r = rq_s[tok*4 + h];
                float x1 = orow[h*64 + j]      * r * gq[h*64 + j];
                float x2 = orow[h*64 + j + 32] * r * gq[h*64 + j + 32];
                g_Q[qbase + h*64 + j]      = x1*cs - x2*sn;
                g_Q[qbase + h*64 + j + 32] = x1*sn + x2*cs;
            }
        }
        // sliding K/V rope at pos TC + t
        for (int i = tid; i < 16 * 32; i += 384) {
            int tok = i >> 5, j = i & 31;
            int t = t0 + tok, pos = TC + t;
            float sn, cs;
            sincosf((float)pos * invf_s[j], &sn, &cs);
            float r = rkv_s[tok];
            float x1 = o_s[tok*384 + 256 + j]      * r;
            float x2 = o_s[tok*384 + 256 + j + 32] * r;
            float k1 = x1*gk[j], k2 = x2*gk[j+32];
            float v1 = x1*gv[j], v2 = x2*gv[j+32];
            size_t o = ((size_t)b*SEQ + pos) * 64;
            g_K[o + j]      = k1*cs - k2*sn;
            g_K[o + j + 32] = k1*sn + k2*cs;
            g_V[o + j]      = v1*cs - v2*sn;
            g_V[o + j + 32] = v1*sn + v2*cs;
        }
        // Q_I = H_dc @ W_IUQ  (H_dc = cols 320..383)
        for (int i = tid; i < 16 * 128; i += 384) {
            int tok = i >> 7, c = i & 127;
            const float* hd = &o_s[tok*384 + 320];
            float a = 0.f;
#pragma unroll 4
            for (int k = 0; k < 64; k++) a += hd[k] * W_IUQ[k*128 + c];
            g_QI[((size_t)b*TLEN + t0 + tok) * 128 + c] = a;
        }
        if (tid < 64) {                        // W_Iw = H_dc @ W_w
            int tok = tid >> 2, c = tid & 3;
            const float* hd = &o_s[tok*384 + 320];
            float a = 0.f;
            for (int k = 0; k < 64; k++) a += hd[k] * W_w[k*4 + c];
            g_WIw[((size_t)b*TLEN + t0 + tok) * 4 + c] = a;
        }
    } else {
        // ======================= compress path =============================
        float* win    = sm;          // 9216
        float* comp_s = sm + 9216;   // 512
        float* red_s  = sm + 9728;   // 1536
        float* rms_s  = sm + 11264;  // 8
        const int cb = blockIdx.x - 256;
        const int b  = cb >> 6;
        const int s0 = (cb & 63) << 3;
        const int row0 = s0 << 2;

        for (int i = tid; i < 36 * DIM; i += 384) {
            int r = row0 + (i >> 8);
            win[i] = (r < TLEN) ? H[((size_t)b*TLEN + r) * DIM + (i & 255)] : 0.f;
        }
        __syncthreads();

        const int col = tid % 96;
        const int sub = tid / 96;
        const int grp = sub >> 1;
        const int kh  = sub & 1;
        const int ds0 = grp << 2;
        const float* Wcol; int ldw;
        if (col < 64) { Wcol = Wc_comp + col;       ldw = 64; }
        else          { Wcol = Wc_idx + (col - 64); ldw = 32; }

        float a0 = 0.f, a1 = 0.f, a2 = 0.f, a3 = 0.f;
        const int k4b = kh << 8;
        for (int k4 = k4b; k4 < k4b + 256; k4++) {
            float w0 = Wcol[(size_t)(4*k4+0) * ldw];
            float w1 = Wcol[(size_t)(4*k4+1) * ldw];
            float w2 = Wcol[(size_t)(4*k4+2) * ldw];
            float w3 = Wcol[(size_t)(4*k4+3) * ldw];
            int lrow = k4 >> 6;
            int coff = (k4 & 63) << 2;
#pragma unroll
            for (int d = 0; d < 4; d++) {
                const float4 wv = *(const float4*)&win[(4*(ds0+d) + lrow) * DIM + coff];
                float s = wv.x*w0 + wv.y*w1 + wv.z*w2 + wv.w*w3;
                if (d == 0) a0 += s; else if (d == 1) a1 += s;
                else if (d == 2) a2 += s; else a3 += s;
            }
        }
        *(float4*)&red_s[(sub*96 + col) * 4] = make_float4(a0, a1, a2, a3);
        __syncthreads();
        if (kh == 0) {
            float4 mine = *(const float4*)&red_s[(sub*96 + col) * 4];
            float4 othr = *(const float4*)&red_s[((sub+1)*96 + col) * 4];
            float av[4] = { mine.x + othr.x, mine.y + othr.y,
                            mine.z + othr.z, mine.w + othr.w };
#pragma unroll
            for (int d = 0; d < 4; d++) {
                int ds = ds0 + d;
                if (col < 64) comp_s[ds*64 + col] = av[d];
                else g_KI[((size_t)b*TC + s0 + ds) * 32 + (col - 64)] = av[d];
            }
        }
        __syncthreads();
        if (tid < 8) {
            float ss = 0.f;
            for (int c = 0; c < 64; c++) { float v = comp_s[tid*64 + c]; ss += v*v; }
            rms_s[tid] = rsqrtf(ss * (1.f/64.f) + 1e-6f);
        }
        __syncthreads();
        for (int i = tid; i < 8 * 32; i += 384) {
            int ds = i >> 5, j = i & 31;
            int pos = s0 + ds;
            float sn, cs;
            sincosf((float)pos * invf_s[j], &sn, &cs);
            float r = rms_s[ds];
            float x1 = comp_s[ds*64 + j] * r, x2 = comp_s[ds*64 + j + 32] * r;
            float k1 = x1*gk[j], k2 = x2*gk[j+32];
            float v1 = x1*gv[j], v2 = x2*gv[j+32];
            size_t o = ((size_t)b*SEQ + pos) * 64;
            g_K[o + j]      = k1*cs - k2*sn;
            g_K[o + j + 32] = k1*sn + k2*cs;
            g_V[o + j]      = v1*cs - v2*sn;
            g_V[o + j + 32] = v1*sn + v2*cs;
        }
    }
}

// ------------------ K2: fused scores + topk + attention + projections ------
// phase-1 smem (floats): qi[0,2112) ki[2112,6208) i_s[6208,14432)
// phase-2 smem:          qo[0,4096) kK[4096,6204) vV[6208,8316)
//                        g_s[8320,10368) p_s[10368,11904)
// persistent:            top_s (ints) at [14432,14560)
#define ISTRIDE 514
#define KVPAD   68
static __device__ __forceinline__ unsigned long long packkey(float v, int s)
{
    unsigned u = __float_as_uint(v);
    u = (u & 0x80000000u) ? ~u : (u | 0x80000000u);
    return ((unsigned long long)u << 32) | (unsigned)(511 - s);
}

__global__ __launch_bounds__(512, 2) void k_main(
    const float* __restrict__ Wg0, const float* __restrict__ bg0,
    const float* __restrict__ Wg1, const float* __restrict__ bg1,
    const float* __restrict__ Wout, const float* __restrict__ bout,
    float* __restrict__ OUT)
{
    extern __shared__ float dsm[];
    __shared__ float invf_s[32];
    float* qi_s = dsm;
    float* ki_s = dsm + 2112;
    float* i_s  = dsm + 6208;
    float* qo_s = dsm;
    float* kK_s = dsm + 4096;
    float* vV_s = dsm + 6208;
    float* g_s  = dsm + 8320;
    float* p_s  = dsm + 10368;
    int*   top_s = (int*)(dsm + 14432);

    const int tid = threadIdx.x;
    const int b  = blockIdx.x >> 7;
    const int r  = blockIdx.x & 127;
    const int t0 = (127 - r) << 4;                 // heavy blocks first
    const int nchunk = ((((t0 + 15) >> 2) + 1) + 127) >> 7;

    if (tid < 32)
        invf_s[tid] = (float)pow(10000.0, -(double)tid / 32.0);

    // ---------------- phase 1: index scores ----------------
    for (int i = tid; i < 16 * 128; i += 512)
        qi_s[(i >> 7) * 132 + (i & 127)] =
            g_QI[((size_t)b*TLEN + t0 + (i >> 7)) * 128 + (i & 127)];

    const int tok  = tid & 15;
    const int sgrp = tid >> 4;                     // 0..31, 4 s-values each
    const float4 wIw = *(const float4*)&g_WIw[((size_t)b*TLEN + t0 + tok) * 4];

    for (int c = 0; c < nchunk; c++) {
        const int s0 = c << 7;
        __syncthreads();
        for (int i = tid; i < 128 * 32; i += 512)
            ki_s[i] = g_KI[((size_t)b*TC + s0) * 32 + i];
        __syncthreads();

        float acc[4][4];
#pragma unroll
        for (int h = 0; h < 4; h++)
#pragma unroll
            for (int j = 0; j < 4; j++) acc[h][j] = 0.f;
#pragma unroll
        for (int c4 = 0; c4 < 8; c4++) {
            float4 q4[4];
#pragma unroll
            for (int h = 0; h < 4; h++)
                q4[h] = *(const float4*)&qi_s[tok*132 + h*32 + c4*4];
#pragma unroll
            for (int j = 0; j < 4; j++) {
                const float4 kv = *(const float4*)&ki_s[(sgrp*4 + j)*32 + c4*4];
#pragma unroll
                for (int h = 0; h < 4; h++)
                    acc[h][j] += q4[h].x*kv.x + q4[h].y*kv.y + q4[h].z*kv.z + q4[h].w*kv.w;
            }
        }
#pragma unroll
        for (int j = 0; j < 4; j++) {
            float v = wIw.x*fmaxf(acc[0][j],0.f) + wIw.y*fmaxf(acc[1][j],0.f)
                    + wIw.z*fmaxf(acc[2][j],0.f) + wIw.w*fmaxf(acc[3][j],0.f);
            i_s[tok*ISTRIDE + s0 + sgrp*4 + j] = v;
        }
    }
    __syncthreads();

    // ---------------- phase 2a: stage qo + sliding K, and top-k ----------
    for (int i = tid; i < 16 * 256; i += 512)
        qo_s[i] = g_Q[((size_t)b*TLEN + t0) * 256 + i];
    for (int i = tid; i < 31 * 64; i += 512) {
        int rel = i >> 6, c = i & 63;
        int row = TC + t0 - 15 + rel;
        kK_s[rel*KVPAD + c] = (row >= TC) ? g_K[((size_t)b*SEQ + row)*64 + c] : 0.f;
    }
    {   // top-k: warp w -> token t0+w (exact jax.lax.top_k semantics)
        const int w = tid >> 5, l = tid & 31;
        const int t = t0 + w;
        const float* Irow = &i_s[w * ISTRIDE];
        unsigned long long keys[16];
#pragma unroll
        for (int k = 0; k < 16; k++) {
            int s = l + 32*k;
            float v = (4*s <= t) ? Irow[s] : fneginf();
            keys[k] = packkey(v, s);
        }
#pragma unroll 1
        for (int i = 0; i < KTOP; i++) {
            unsigned long long best = 0ull;
#pragma unroll
            for (int k = 0; k < 16; k++) best = max(best, keys[k]);
#pragma unroll
            for (int off = 16; off; off >>= 1)
                best = max(best, __shfl_xor_sync(0xffffffffu, best, off));
            int s_win = 511 - (int)(best & 0xffffffffull);
            if (l == 0) top_s[w*8 + i] = s_win;
            if ((s_win & 31) == l) keys[s_win >> 5] = 0ull;
        }
    }
    __syncthreads();

    // ---------------- phase 2b: stage sliding V (overwrites i_s) ----------
    for (int i = tid; i < 31 * 64; i += 512) {
        int rel = i >> 6, c = i & 63;
        int row = TC + t0 - 15 + rel;
        vV_s[rel*KVPAD + c] = (row >= TC) ? g_V[((size_t)b*SEQ + row)*64 + c] : 0.f;
    }
    __syncthreads();

    // ---------------- phase 3: attention ----------------
    {
        const int w = tid >> 5, l = tid & 31;
        const int t = t0 + w;
        const int nsl = (t + 1 < 16) ? (t + 1) : 16;
        const int nkey = 8 + nsl;

        float dh[4] = {0.f, 0.f, 0.f, 0.f};
        bool valid = false;
        if (l < 8) {
            valid = true;
            int row = top_s[w*8 + l];
            const float4* kp = (const float4*)(g_K + ((size_t)b*SEQ + row) * 64);
#pragma unroll
            for (int c4 = 0; c4 < 16; c4++) {
                float4 kv = kp[c4];
#pragma unroll
                for (int h = 0; h < 4; h++) {
                    float4 q4 = *(const float4*)&qo_s[w*256 + h*64 + c4*4];
                    dh[h] += q4.x*kv.x + q4.y*kv.y + q4.z*kv.z + q4.w*kv.w;
                }
            }
        } else if (l < 24) {
            valid = (l < nkey);
            const float4* kp = (const float4*)(kK_s + (w + 23 - l) * KVPAD);
#pragma unroll
            for (int c4 = 0; c4 < 16; c4++) {
                float4 kv = kp[c4];
#pragma unroll
                for (int h = 0; h < 4; h++) {
                    float4 q4 = *(const float4*)&qo_s[w*256 + h*64 + c4*4];
                    dh[h] += q4.x*kv.x + q4.y*kv.y + q4.z*kv.z + q4.w*kv.w;
                }
            }
        }
#pragma unroll
        for (int h = 0; h < 4; h++) {
            float s = valid ? dh[h] * 0.125f : fneginf();
            float m = s;
#pragma unroll
            for (int off = 16; off; off >>= 1)
                m = fmaxf(m, __shfl_xor_sync(0xffffffffu, m, off));
            float e = expf(s - m);
            float sum = e;
#pragma unroll
            for (int off = 16; off; off >>= 1)
                sum += __shfl_xor_sync(0xffffffffu, sum, off);
            float p = e / sum;                 // 0 for invalid lanes
            if (l < 24) p_s[w*96 + h*24 + l] = p;
        }
        __syncwarp();

        float o1[4] = {0,0,0,0}, o2[4] = {0,0,0,0};
#pragma unroll
        for (int j = 0; j < 8; j++) {          // top-k keys: gmem gather
            int rj = top_s[w*8 + j];
            const float* vp = g_V + ((size_t)b*SEQ + rj) * 64;
            float v1 = vp[l], v2 = vp[l + 32];
#pragma unroll
            for (int h = 0; h < 4; h++) {
                float p = p_s[w*96 + h*24 + j];
                o1[h] += p * v1;
                o2[h] += p * v2;
            }
        }
#pragma unroll
        for (int j = 8; j < 24; j++) {         // sliding keys: smem
            const float* vp = vV_s + (w + 23 - j) * KVPAD;
            float v1 = vp[l], v2 = vp[l + 32];
#pragma unroll
            for (int h = 0; h < 4; h++) {
                float p = p_s[w*96 + h*24 + j];
                o1[h] += p * v1;
                o2[h] += p * v2;
            }
        }
        float sn, cs;
        sincosf((float)t * invf_s[l], &sn, &cs);
        __syncwarp();   // all lanes done reading qo_s[w] before overwrite
#pragma unroll
        for (int h = 0; h < 4; h++) {
            qo_s[w*256 + h*64 + l]      =  o1[h]*cs + o2[h]*sn;
            qo_s[w*256 + h*64 + 32 + l] = -o1[h]*sn + o2[h]*cs;
        }
    }
    __syncthreads();

    // ---------------- phase 4: gate projections ----------------
    {
        const int col = tid & 127;
        const int tq  = tid >> 7;               // 4 tokens each
        const int c   = col & 63;
        const float* Wg = (col < 64) ? Wg0 : Wg1;
        const float  bb = (col < 64) ? bg0[c] : bg1[c];
        const int obase = (col < 64) ? 0 : 128;
        float a[4] = {bb, bb, bb, bb};
#pragma unroll 4
        for (int k = 0; k < 128; k++) {
            float wv = Wg[k*64 + c];
#pragma unroll
            for (int u = 0; u < 4; u++)
                a[u] += qo_s[(tq*4 + u)*256 + obase + k] * wv;
        }
#pragma unroll
        for (int u = 0; u < 4; u++) g_s[(tq*4 + u)*128 + col] = a[u];
    }
    __syncthreads();

    // ---------------- phase 5: final projection ----------------
    {
        const int col = tid & 255;
        const int tq  = tid >> 8;               // 8 tokens each
        float bb = bout[col];
        float a[8] = {bb, bb, bb, bb, bb, bb, bb, bb};
#pragma unroll 4
        for (int k = 0; k < 128; k++) {
            float wv = Wout[k*256 + col];
#pragma unroll
            for (int u = 0; u < 8; u++)
                a[u] += g_s[(tq*8 + u)*128 + k] * wv;
        }
#pragma unroll
        for (int u = 0; u < 8; u++)
            OUT[((size_t)b*TLEN + t0 + tq*8 + u) * DIM + col] = a[u];
    }
}

// ----------------------------- launcher ------------------------------------
extern "C" void kernel_launch(void* const* d_in, const int* in_sizes, int n_in,
                              void* d_out, int out_size)
{
    const float* H       = (const float*)d_in[0];
    const float* Wc_comp = (const float*)d_in[1];
    const float* Wc_idx  = (const float*)d_in[2];
    const float* W_DQ    = (const float*)d_in[3];
    const float* W_IUQ   = (const float*)d_in[4];
    const float* W_w     = (const float*)d_in[5];
    const float* W_Q     = (const float*)d_in[6];
    const float* W_KV    = (const float*)d_in[7];
    const float* gq      = (const float*)d_in[8];
    const float* gk      = (const float*)d_in[9];
    const float* gv      = (const float*)d_in[10];
    const float* Wg0     = (const float*)d_in[11];
    const float* bg0     = (const float*)d_in[12];
    const float* Wg1     = (const float*)d_in[13];
    const float* bg1     = (const float*)d_in[14];
    const float* Wout    = (const float*)d_in[15];
    const float* bout    = (const float*)d_in[16];
    float* OUT = (float*)d_out;

    cudaFuncSetAttribute(k_main,
                         cudaFuncAttributeMaxDynamicSharedMemorySize, 58240);

    k_pre<<<256 + 128, 384>>>(H, Wc_comp, Wc_idx, W_DQ, W_IUQ, W_w, W_Q, W_KV,
                              gq, gk, gv);
    k_main<<<BATCH * 128, 512, 58240>>>(Wg0, bg0, Wg1, bg1, Wout, bout, OUT);
}